// round 13
// baseline (speedup 1.0000x reference)
#include <cuda_runtime.h>
#include <cuda_fp16.h>
#include <cstdint>

// GCN layer: out = segment_sum(val * x[col]) @ W^T + b
//  = b + segment_sum(val * (x @ W^T)[col])    (projection commutes with sum)
//
// K1: rowptr boundary pass, 4 edges/thread via int4.
// K2: xW = x @ W^T via mma.sync tf32 (fp32 accum), fp16 epilogue.
// K3: SpMM: 2 warps per node, half2 per lane. Edge metadata loaded ONCE per
//     32 edges by coalesced lane load, broadcast via shfl -> meta off the
//     gather critical path. 8 independent gathers in flight per group.

#define D 128
#define MAX_N 50000
#define SPAD 132            // 128 + 4 padding words -> conflict-free frag loads

__device__ __half g_xWh[MAX_N * D];
__device__ int    g_rowptr[MAX_N + 1];

__device__ __forceinline__ float to_tf32(float f) {
    float r;
    asm("cvt.rna.tf32.f32 %0, %1;" : "=f"(r) : "f"(f));
    return r;
}

__device__ __forceinline__ void mma_tf32(float* d, const uint32_t* a, const uint32_t* b) {
    asm volatile(
        "mma.sync.aligned.m16n8k8.row.col.f32.tf32.tf32.f32 "
        "{%0,%1,%2,%3}, {%4,%5,%6,%7}, {%8,%9}, {%0,%1,%2,%3};"
        : "+f"(d[0]), "+f"(d[1]), "+f"(d[2]), "+f"(d[3])
        : "r"(a[0]), "r"(a[1]), "r"(a[2]), "r"(a[3]), "r"(b[0]), "r"(b[1]));
}

// ---------------------------------------------------------------------------
// K1: CSR offsets from sorted edge_row. Thread t covers edges [4t, 4t+4).
// ---------------------------------------------------------------------------
__global__ void rowptr_from_sorted(const int* __restrict__ rows, int E, int N) {
    const int base = (blockIdx.x * blockDim.x + threadIdx.x) * 4;
    if (base >= E) return;

    int prev = (base == 0) ? -1 : __ldg(rows + base - 1);
    if (base + 4 <= E) {
        const int4 c = __ldg(reinterpret_cast<const int4*>(rows + base));
        const int rc[4] = {c.x, c.y, c.z, c.w};
        #pragma unroll
        for (int j = 0; j < 4; j++) {
            for (int r = prev; r < rc[j]; r++) g_rowptr[r + 1] = base + j;
            prev = rc[j];
        }
        if (base + 4 == E)
            for (int r = prev; r < N; r++) g_rowptr[r + 1] = E;
    } else {
        for (int j = 0; j < E - base; j++) {
            const int cur = __ldg(rows + base + j);
            for (int r = prev; r < cur; r++) g_rowptr[r + 1] = base + j;
            prev = cur;
        }
        for (int r = prev; r < N; r++) g_rowptr[r + 1] = E;
    }
    if (base == 0) g_rowptr[0] = 0;
}

// ---------------------------------------------------------------------------
// K2: xW[i, o] = sum_k x[i,k] * W[o,k], stored as fp16.
// 128x128 tile per CTA, 256 threads = 8 warps (4x2), warp tile 32x64.
// ---------------------------------------------------------------------------
__global__ __launch_bounds__(256, 1)
void gemm_xw_mma(const float* __restrict__ x, const float* __restrict__ W, int N) {
    extern __shared__ float smem[];
    float* As = smem;                 // [128][SPAD]
    float* Ws = smem + 128 * SPAD;    // [128][SPAD]

    const int tid = threadIdx.x;
    const int block_row = blockIdx.x * 128;

    #pragma unroll
    for (int it = 0; it < 16; it++) {
        const int slot = tid + it * 256;        // float4 slot, 4096 total
        const int r = slot >> 5;
        const int c = (slot & 31) * 4;
        const int gr = block_row + r;
        float4 v = make_float4(0.f, 0.f, 0.f, 0.f);
        if (gr < N) v = *reinterpret_cast<const float4*>(x + (size_t)gr * D + c);
        float* dst = As + r * SPAD + c;
        dst[0] = to_tf32(v.x); dst[1] = to_tf32(v.y);
        dst[2] = to_tf32(v.z); dst[3] = to_tf32(v.w);
    }
    #pragma unroll
    for (int it = 0; it < 16; it++) {
        const int slot = tid + it * 256;
        const int r = slot >> 5;
        const int c = (slot & 31) * 4;
        float4 v = *reinterpret_cast<const float4*>(W + (size_t)r * D + c);
        float* dst = Ws + r * SPAD + c;
        dst[0] = to_tf32(v.x); dst[1] = to_tf32(v.y);
        dst[2] = to_tf32(v.z); dst[3] = to_tf32(v.w);
    }
    __syncthreads();

    const uint32_t* Ab = reinterpret_cast<const uint32_t*>(As);
    const uint32_t* Wb = reinterpret_cast<const uint32_t*>(Ws);

    const int wid  = tid >> 5;
    const int lane = tid & 31;
    const int grp  = lane >> 2;       // 0..7
    const int tig  = lane & 3;        // 0..3
    const int warpRow = (wid & 3) * 32;
    const int warpCol = (wid >> 2) * 64;

    float acc[2][8][4];
    #pragma unroll
    for (int mt = 0; mt < 2; mt++)
        #pragma unroll
        for (int nt = 0; nt < 8; nt++)
            #pragma unroll
            for (int q = 0; q < 4; q++) acc[mt][nt][q] = 0.f;

    #pragma unroll
    for (int ks = 0; ks < 16; ks++) {
        const int k0 = ks * 8;
        uint32_t a[2][4];
        #pragma unroll
        for (int mt = 0; mt < 2; mt++) {
            const int r0 = warpRow + mt * 16 + grp;
            a[mt][0] = Ab[r0 * SPAD + k0 + tig];
            a[mt][1] = Ab[(r0 + 8) * SPAD + k0 + tig];
            a[mt][2] = Ab[r0 * SPAD + k0 + tig + 4];
            a[mt][3] = Ab[(r0 + 8) * SPAD + k0 + tig + 4];
        }
        uint32_t b[8][2];
        #pragma unroll
        for (int nt = 0; nt < 8; nt++) {
            const int n0 = warpCol + nt * 8 + grp;
            b[nt][0] = Wb[n0 * SPAD + k0 + tig];
            b[nt][1] = Wb[n0 * SPAD + k0 + tig + 4];
        }
        #pragma unroll
        for (int mt = 0; mt < 2; mt++)
            #pragma unroll
            for (int nt = 0; nt < 8; nt++)
                mma_tf32(acc[mt][nt], a[mt], b[nt]);
    }

    #pragma unroll
    for (int mt = 0; mt < 2; mt++) {
        const int r0 = block_row + warpRow + mt * 16 + grp;
        #pragma unroll
        for (int nt = 0; nt < 8; nt++) {
            const int c0 = warpCol + nt * 8 + tig * 2;
            if (r0 < N)
                *reinterpret_cast<__half2*>(g_xWh + (size_t)r0 * D + c0) =
                    __floats2half2_rn(acc[mt][nt][0], acc[mt][nt][1]);
            if (r0 + 8 < N)
                *reinterpret_cast<__half2*>(g_xWh + (size_t)(r0 + 8) * D + c0) =
                    __floats2half2_rn(acc[mt][nt][2], acc[mt][nt][3]);
        }
    }
}

// ---------------------------------------------------------------------------
// K3: out[i] = b + sum_{e in [rp[i], rp[i+1])} val[e] * xW[col[e]]
// 2 warps per node: warp half h owns dims [h*64, h*64+64), half2 per lane.
// Metadata: coalesced lane load of 32 edges, shfl-broadcast to all lanes.
// ---------------------------------------------------------------------------
#define FMA2(ACC, V, A) \
    do { ACC.x = fmaf(V, A.x, ACC.x); ACC.y = fmaf(V, A.y, ACC.y); } while (0)

__global__ __launch_bounds__(256)
void spmm_kernel(const int* __restrict__ ecol, const float* __restrict__ eval,
                 const float* __restrict__ b, float* __restrict__ out, int N) {
    const int gwarp = (blockIdx.x * blockDim.x + threadIdx.x) >> 5;
    const int node  = gwarp >> 1;
    const int half  = gwarp & 1;
    const int lane  = threadIdx.x & 31;
    if (node >= N) return;

    const int start = g_rowptr[node];
    const int end   = g_rowptr[node + 1];

    const int dim = half * 64 + lane * 2;
    const __half* xw = g_xWh + dim;

    float2 acc0 = *reinterpret_cast<const float2*>(b + dim);
    float2 acc1 = make_float2(0.f, 0.f);

    for (int base = start; base < end; base += 32) {
        const int n = min(32, end - base);

        // one coalesced metadata load covers up to 32 edges
        int   mc = 0;
        float mv = 0.f;
        if (lane < n) {
            mc = __ldg(ecol + base + lane);
            mv = __ldg(eval + base + lane);
        }

        int j = 0;
        // 8-edge groups: 16 shfls (cheap) + 8 independent one-line gathers
        for (; j + 8 <= n; j += 8) {
            int   c[8];
            float v[8];
            #pragma unroll
            for (int q = 0; q < 8; q++) {
                c[q] = __shfl_sync(0xFFFFFFFFu, mc, j + q);
                v[q] = __shfl_sync(0xFFFFFFFFu, mv, j + q);
            }
            __half2 h[8];
            #pragma unroll
            for (int q = 0; q < 8; q++)
                h[q] = *reinterpret_cast<const __half2*>(xw + (size_t)c[q] * D);
            #pragma unroll
            for (int q = 0; q < 8; q++) {
                const float2 a = __half22float2(h[q]);
                if (q & 1) FMA2(acc1, v[q], a);
                else       FMA2(acc0, v[q], a);
            }
        }
        // remainder of this 32-edge window
        for (; j < n; j++) {
            const int   c = __shfl_sync(0xFFFFFFFFu, mc, j);
            const float v = __shfl_sync(0xFFFFFFFFu, mv, j);
            const float2 a = __half22float2(
                *reinterpret_cast<const __half2*>(xw + (size_t)c * D));
            FMA2(acc0, v, a);
        }
    }

    acc0.x += acc1.x; acc0.y += acc1.y;
    *reinterpret_cast<float2*>(out + (size_t)node * D + dim) = acc0;
}

// ---------------------------------------------------------------------------
extern "C" void kernel_launch(void* const* d_in, const int* in_sizes, int n_in,
                              void* d_out, int out_size) {
    const float* x    = (const float*)d_in[0];
    const int*   erow = (const int*)  d_in[1];
    const int*   ecol = (const int*)  d_in[2];
    const float* eval = (const float*)d_in[3];
    const float* W    = (const float*)d_in[4];
    const float* b    = (const float*)d_in[5];

    const int N = in_sizes[0] / D;
    const int E = in_sizes[1];

    const int smem_bytes = 2 * 128 * SPAD * sizeof(float);   // ~135 KB
    cudaFuncSetAttribute(gemm_xw_mma, cudaFuncAttributeMaxDynamicSharedMemorySize, smem_bytes);

    const int rp_threads = (E + 3) / 4;
    rowptr_from_sorted<<<(rp_threads + 255) / 256, 256>>>(erow, E, N);
    gemm_xw_mma<<<(N + 127) / 128, 256, smem_bytes>>>(x, W, N);

    const int total_warps = 2 * N;                 // 2 warps per node
    spmm_kernel<<<(total_warps * 32 + 255) / 256, 256>>>(ecol, eval, b, (float*)d_out, N);
}

// round 14
// speedup vs baseline: 1.2185x; 1.2185x over previous
#include <cuda_runtime.h>
#include <cuda_fp16.h>
#include <cstdint>

// GCN layer: out = segment_sum(val * x[col]) @ W^T + b
//  = b + segment_sum(val * (x @ W^T)[col])    (projection commutes with sum)
//
// K1: rowptr boundary pass, 4 edges/thread via int4.
// K2: xW = x @ W^T via mma.sync tf32 (fp32 accum), fp16 epilogue.
// K3: SpMM: 2 warps per node SPLIT BY EDGES (each warp: half the edges, all
//     128 dims, 4 dims/lane via one 8B load). Serial chain per warp halves.
//     Partials combined through smem.

#define D 128
#define MAX_N 50000
#define SPAD 132            // 128 + 4 padding words -> conflict-free frag loads

__device__ __half g_xWh[MAX_N * D];
__device__ int    g_rowptr[MAX_N + 1];

__device__ __forceinline__ float to_tf32(float f) {
    float r;
    asm("cvt.rna.tf32.f32 %0, %1;" : "=f"(r) : "f"(f));
    return r;
}

__device__ __forceinline__ void mma_tf32(float* d, const uint32_t* a, const uint32_t* b) {
    asm volatile(
        "mma.sync.aligned.m16n8k8.row.col.f32.tf32.tf32.f32 "
        "{%0,%1,%2,%3}, {%4,%5,%6,%7}, {%8,%9}, {%0,%1,%2,%3};"
        : "+f"(d[0]), "+f"(d[1]), "+f"(d[2]), "+f"(d[3])
        : "r"(a[0]), "r"(a[1]), "r"(a[2]), "r"(a[3]), "r"(b[0]), "r"(b[1]));
}

// ---------------------------------------------------------------------------
// K1: CSR offsets from sorted edge_row. Thread t covers edges [4t, 4t+4).
// ---------------------------------------------------------------------------
__global__ void rowptr_from_sorted(const int* __restrict__ rows, int E, int N) {
    const int base = (blockIdx.x * blockDim.x + threadIdx.x) * 4;
    if (base >= E) return;

    int prev = (base == 0) ? -1 : __ldg(rows + base - 1);
    if (base + 4 <= E) {
        const int4 c = __ldg(reinterpret_cast<const int4*>(rows + base));
        const int rc[4] = {c.x, c.y, c.z, c.w};
        #pragma unroll
        for (int j = 0; j < 4; j++) {
            for (int r = prev; r < rc[j]; r++) g_rowptr[r + 1] = base + j;
            prev = rc[j];
        }
        if (base + 4 == E)
            for (int r = prev; r < N; r++) g_rowptr[r + 1] = E;
    } else {
        for (int j = 0; j < E - base; j++) {
            const int cur = __ldg(rows + base + j);
            for (int r = prev; r < cur; r++) g_rowptr[r + 1] = base + j;
            prev = cur;
        }
        for (int r = prev; r < N; r++) g_rowptr[r + 1] = E;
    }
    if (base == 0) g_rowptr[0] = 0;
}

// ---------------------------------------------------------------------------
// K2: xW[i, o] = sum_k x[i,k] * W[o,k], stored as fp16.
// 128x128 tile per CTA, 256 threads = 8 warps (4x2), warp tile 32x64.
// ---------------------------------------------------------------------------
__global__ __launch_bounds__(256, 1)
void gemm_xw_mma(const float* __restrict__ x, const float* __restrict__ W, int N) {
    extern __shared__ float smem[];
    float* As = smem;                 // [128][SPAD]
    float* Ws = smem + 128 * SPAD;    // [128][SPAD]

    const int tid = threadIdx.x;
    const int block_row = blockIdx.x * 128;

    #pragma unroll
    for (int it = 0; it < 16; it++) {
        const int slot = tid + it * 256;        // float4 slot, 4096 total
        const int r = slot >> 5;
        const int c = (slot & 31) * 4;
        const int gr = block_row + r;
        float4 v = make_float4(0.f, 0.f, 0.f, 0.f);
        if (gr < N) v = *reinterpret_cast<const float4*>(x + (size_t)gr * D + c);
        float* dst = As + r * SPAD + c;
        dst[0] = to_tf32(v.x); dst[1] = to_tf32(v.y);
        dst[2] = to_tf32(v.z); dst[3] = to_tf32(v.w);
    }
    #pragma unroll
    for (int it = 0; it < 16; it++) {
        const int slot = tid + it * 256;
        const int r = slot >> 5;
        const int c = (slot & 31) * 4;
        float4 v = *reinterpret_cast<const float4*>(W + (size_t)r * D + c);
        float* dst = Ws + r * SPAD + c;
        dst[0] = to_tf32(v.x); dst[1] = to_tf32(v.y);
        dst[2] = to_tf32(v.z); dst[3] = to_tf32(v.w);
    }
    __syncthreads();

    const uint32_t* Ab = reinterpret_cast<const uint32_t*>(As);
    const uint32_t* Wb = reinterpret_cast<const uint32_t*>(Ws);

    const int wid  = tid >> 5;
    const int lane = tid & 31;
    const int grp  = lane >> 2;       // 0..7
    const int tig  = lane & 3;        // 0..3
    const int warpRow = (wid & 3) * 32;
    const int warpCol = (wid >> 2) * 64;

    float acc[2][8][4];
    #pragma unroll
    for (int mt = 0; mt < 2; mt++)
        #pragma unroll
        for (int nt = 0; nt < 8; nt++)
            #pragma unroll
            for (int q = 0; q < 4; q++) acc[mt][nt][q] = 0.f;

    #pragma unroll
    for (int ks = 0; ks < 16; ks++) {
        const int k0 = ks * 8;
        uint32_t a[2][4];
        #pragma unroll
        for (int mt = 0; mt < 2; mt++) {
            const int r0 = warpRow + mt * 16 + grp;
            a[mt][0] = Ab[r0 * SPAD + k0 + tig];
            a[mt][1] = Ab[(r0 + 8) * SPAD + k0 + tig];
            a[mt][2] = Ab[r0 * SPAD + k0 + tig + 4];
            a[mt][3] = Ab[(r0 + 8) * SPAD + k0 + tig + 4];
        }
        uint32_t b[8][2];
        #pragma unroll
        for (int nt = 0; nt < 8; nt++) {
            const int n0 = warpCol + nt * 8 + grp;
            b[nt][0] = Wb[n0 * SPAD + k0 + tig];
            b[nt][1] = Wb[n0 * SPAD + k0 + tig + 4];
        }
        #pragma unroll
        for (int mt = 0; mt < 2; mt++)
            #pragma unroll
            for (int nt = 0; nt < 8; nt++)
                mma_tf32(acc[mt][nt], a[mt], b[nt]);
    }

    #pragma unroll
    for (int mt = 0; mt < 2; mt++) {
        const int r0 = block_row + warpRow + mt * 16 + grp;
        #pragma unroll
        for (int nt = 0; nt < 8; nt++) {
            const int c0 = warpCol + nt * 8 + tig * 2;
            if (r0 < N)
                *reinterpret_cast<__half2*>(g_xWh + (size_t)r0 * D + c0) =
                    __floats2half2_rn(acc[mt][nt][0], acc[mt][nt][1]);
            if (r0 + 8 < N)
                *reinterpret_cast<__half2*>(g_xWh + (size_t)(r0 + 8) * D + c0) =
                    __floats2half2_rn(acc[mt][nt][2], acc[mt][nt][3]);
        }
    }
}

// ---------------------------------------------------------------------------
// K3: out[i] = b + sum_{e in [rp[i], rp[i+1])} val[e] * xW[col[e]]
// Block = 8 warps = 4 nodes. Warp pair (2w, 2w+1) -> node w: warp takes half
// the edge range, all 128 dims (lane owns dims [4*lane, 4*lane+4) = 8B load).
// Partials combined via smem; warp 0 of the pair adds bias and stores.
// ---------------------------------------------------------------------------
__device__ __forceinline__ float4 h4_to_f4(uint2 u) {
    const __half2 lo = *reinterpret_cast<const __half2*>(&u.x);
    const __half2 hi = *reinterpret_cast<const __half2*>(&u.y);
    const float2 a = __half22float2(lo);
    const float2 c = __half22float2(hi);
    return make_float4(a.x, a.y, c.x, c.y);
}
#define FMA4(ACC, V, A) \
    do { ACC.x = fmaf(V, A.x, ACC.x); ACC.y = fmaf(V, A.y, ACC.y); \
         ACC.z = fmaf(V, A.z, ACC.z); ACC.w = fmaf(V, A.w, ACC.w); } while (0)

__global__ __launch_bounds__(256)
void spmm_kernel(const int* __restrict__ ecol, const float* __restrict__ eval,
                 const float* __restrict__ b, float* __restrict__ out, int N) {
    __shared__ float4 part[4][32];

    const int wid   = threadIdx.x >> 5;       // 0..7
    const int lane  = threadIdx.x & 31;
    const int nib   = wid >> 1;               // node-in-block 0..3
    const int ehalf = wid & 1;
    const int node  = blockIdx.x * 4 + nib;
    const bool valid = node < N;

    int start = 0, end = 0;
    if (valid) {
        const int s = g_rowptr[node];
        const int t = g_rowptr[node + 1];
        const int mid = (s + t) >> 1;
        start = ehalf ? mid : s;
        end   = ehalf ? t   : mid;
    }

    const __half* xw = g_xWh + lane * 4;      // lane's 4-dim slice (8 bytes)

    float4 acc0 = make_float4(0.f, 0.f, 0.f, 0.f);
    float4 acc1 = make_float4(0.f, 0.f, 0.f, 0.f);

    int e = start;
    while (e < end && (e & 3)) {              // peel to 4-alignment
        const uint2 u = *reinterpret_cast<const uint2*>(xw + (size_t)__ldg(ecol + e) * D);
        FMA4(acc0, __ldg(eval + e), h4_to_f4(u));
        e++;
    }
    for (; e + 4 <= end; e += 4) {            // 4 edges, 4 independent 8B gathers
        const int4   c = __ldg(reinterpret_cast<const int4*>(ecol + e));
        const float4 v = __ldg(reinterpret_cast<const float4*>(eval + e));
        const uint2 u0 = *reinterpret_cast<const uint2*>(xw + (size_t)c.x * D);
        const uint2 u1 = *reinterpret_cast<const uint2*>(xw + (size_t)c.y * D);
        const uint2 u2 = *reinterpret_cast<const uint2*>(xw + (size_t)c.z * D);
        const uint2 u3 = *reinterpret_cast<const uint2*>(xw + (size_t)c.w * D);
        FMA4(acc0, v.x, h4_to_f4(u0)); FMA4(acc1, v.y, h4_to_f4(u1));
        FMA4(acc0, v.z, h4_to_f4(u2)); FMA4(acc1, v.w, h4_to_f4(u3));
    }
    while (e < end) {                         // tail
        const uint2 u = *reinterpret_cast<const uint2*>(xw + (size_t)__ldg(ecol + e) * D);
        FMA4(acc0, __ldg(eval + e), h4_to_f4(u));
        e++;
    }

    acc0.x += acc1.x; acc0.y += acc1.y; acc0.z += acc1.z; acc0.w += acc1.w;

    // combine the two edge-halves through smem
    if (ehalf) part[nib][lane] = acc0;
    __syncthreads();
    if (!ehalf && valid) {
        const float4 p  = part[nib][lane];
        const float4 bb = *reinterpret_cast<const float4*>(b + lane * 4);
        acc0.x += p.x + bb.x; acc0.y += p.y + bb.y;
        acc0.z += p.z + bb.z; acc0.w += p.w + bb.w;
        *reinterpret_cast<float4*>(out + (size_t)node * D + lane * 4) = acc0;
    }
}

// ---------------------------------------------------------------------------
extern "C" void kernel_launch(void* const* d_in, const int* in_sizes, int n_in,
                              void* d_out, int out_size) {
    const float* x    = (const float*)d_in[0];
    const int*   erow = (const int*)  d_in[1];
    const int*   ecol = (const int*)  d_in[2];
    const float* eval = (const float*)d_in[3];
    const float* W    = (const float*)d_in[4];
    const float* b    = (const float*)d_in[5];

    const int N = in_sizes[0] / D;
    const int E = in_sizes[1];

    const int smem_bytes = 2 * 128 * SPAD * sizeof(float);   // ~135 KB
    cudaFuncSetAttribute(gemm_xw_mma, cudaFuncAttributeMaxDynamicSharedMemorySize, smem_bytes);

    const int rp_threads = (E + 3) / 4;
    rowptr_from_sorted<<<(rp_threads + 255) / 256, 256>>>(erow, E, N);
    gemm_xw_mma<<<(N + 127) / 128, 256, smem_bytes>>>(x, W, N);

    spmm_kernel<<<(N + 3) / 4, 256>>>(ecol, eval, b, (float*)d_out, N);
}